// round 1
// baseline (speedup 1.0000x reference)
#include <cuda_runtime.h>
#include <math.h>
#include <stdint.h>

// ---------------- problem constants ----------------
#define M_ROWS 100352            // B * N = 8 * 12544
#define NWIN   256               // 16 * 16 windows
// window size 7, shift 3, H=W=112, C=256, NH=8, hd=32

// ---------------- scratch (static device globals; no allocations) ----------
__device__ float g_xln [(size_t)M_ROWS * 256];   // LN output (reused for LN1 and LN2)
__device__ float g_qkv [(size_t)M_ROWS * 768];   // qkv in window-row order
__device__ float g_attn[(size_t)M_ROWS * 256];   // attention output, window-row order
__device__ float g_hid [(size_t)M_ROWS * 1024];  // MLP hidden
__device__ int   g_map [M_ROWS];                 // window-row -> global-row bijection

// ---------------- window/roll permutation map ----------------
// window row i = ((b*256 + wh*16+ww)*49 + ii*7+jj)
// gathers from global row b*12544 + ((wh*7+ii+3)%112)*112 + ((ww*7+jj+3)%112)
__global__ void build_map_kernel(int* __restrict__ map) {
    int i = blockIdx.x * 256 + threadIdx.x;
    if (i >= M_ROWS) return;
    int b   = i / (NWIN * 49);
    int rem = i - b * (NWIN * 49);
    int w   = rem / 49;
    int p   = rem - w * 49;
    int wh = w >> 4, ww = w & 15;
    int ii = p / 7,  jj = p - ii * 7;
    int h  = wh * 7 + ii + 3; if (h  >= 112) h  -= 112;
    int wg = ww * 7 + jj + 3; if (wg >= 112) wg -= 112;
    map[i] = b * 12544 + h * 112 + wg;
}

// ---------------- LayerNorm: one warp per row (C=256, 8 elems/lane) --------
__global__ void __launch_bounds__(256) ln_kernel(
    const float* __restrict__ x, const float* __restrict__ gamma,
    const float* __restrict__ beta, float* __restrict__ out)
{
    int row  = (blockIdx.x * 256 + threadIdx.x) >> 5;
    int lane = threadIdx.x & 31;
    const float* xr = x + (size_t)row * 256 + lane * 8;
    float4 a = *(const float4*)(xr);
    float4 c = *(const float4*)(xr + 4);
    float s  = a.x + a.y + a.z + a.w + c.x + c.y + c.z + c.w;
    float sq = a.x*a.x + a.y*a.y + a.z*a.z + a.w*a.w
             + c.x*c.x + c.y*c.y + c.z*c.z + c.w*c.w;
#pragma unroll
    for (int o = 16; o; o >>= 1) {
        s  += __shfl_xor_sync(0xffffffffu, s,  o);
        sq += __shfl_xor_sync(0xffffffffu, sq, o);
    }
    float mean = s  * (1.0f / 256.0f);
    float var  = sq * (1.0f / 256.0f) - mean * mean;
    float rstd = rsqrtf(var + 1e-5f);
    float4 g0 = *(const float4*)(gamma + lane * 8);
    float4 g1 = *(const float4*)(gamma + lane * 8 + 4);
    float4 b0 = *(const float4*)(beta  + lane * 8);
    float4 b1 = *(const float4*)(beta  + lane * 8 + 4);
    float4 r0, r1;
    r0.x = (a.x - mean) * rstd * g0.x + b0.x;
    r0.y = (a.y - mean) * rstd * g0.y + b0.y;
    r0.z = (a.z - mean) * rstd * g0.z + b0.z;
    r0.w = (a.w - mean) * rstd * g0.w + b0.w;
    r1.x = (c.x - mean) * rstd * g1.x + b1.x;
    r1.y = (c.y - mean) * rstd * g1.y + b1.y;
    r1.z = (c.z - mean) * rstd * g1.z + b1.z;
    r1.w = (c.w - mean) * rstd * g1.w + b1.w;
    float* orow = out + (size_t)row * 256 + lane * 8;
    *(float4*)(orow)     = r0;
    *(float4*)(orow + 4) = r1;
}

// ---------------- tiled SGEMM 128x128x16, 256 thr, 8x8 per thread ----------
// EPI: 0 = bias; 1 = bias+GELU(exact erf); 2 = bias + scatter(map) + residual
//      from `resid`; 3 = bias + in-place residual (Cout read+write)
template<bool GATHER_A, int EPI>
__global__ void __launch_bounds__(256) sgemm_kernel(
    const float* __restrict__ A, const float* __restrict__ B,
    const float* __restrict__ bias, float* __restrict__ Cout,
    const float* __restrict__ resid, const int* __restrict__ map,
    int Kdim, int Ncols)
{
    __shared__ float As[16][128];
    __shared__ float Bs[16][128];
    const int tid = threadIdx.x;
    const int tx  = tid & 15;
    const int ty  = tid >> 4;
    const int rowBase = blockIdx.y * 128;
    const int colBase = blockIdx.x * 128;

    float acc[8][8];
#pragma unroll
    for (int i = 0; i < 8; i++)
#pragma unroll
        for (int j = 0; j < 8; j++) acc[i][j] = 0.0f;

    // A-load assignment: 512 float4 per tile, 2 per thread
    const int a_r0 = tid >> 2;          // rows 0..63
    const int a_r1 = a_r0 + 64;         // rows 64..127
    const int a_c0 = (tid & 3) * 4;
    int garow0 = rowBase + a_r0;
    int garow1 = rowBase + a_r1;
    if (GATHER_A) { garow0 = map[garow0]; garow1 = map[garow1]; }
    const float* Ap0 = A + (size_t)garow0 * Kdim + a_c0;
    const float* Ap1 = A + (size_t)garow1 * Kdim + a_c0;

    const int b_r = tid >> 5;           // rows 0..7 (+8)
    const int b_c = (tid & 31) * 4;

    for (int k0 = 0; k0 < Kdim; k0 += 16) {
        float4 av0 = *(const float4*)(Ap0 + k0);
        float4 av1 = *(const float4*)(Ap1 + k0);
        As[a_c0 + 0][a_r0] = av0.x; As[a_c0 + 1][a_r0] = av0.y;
        As[a_c0 + 2][a_r0] = av0.z; As[a_c0 + 3][a_r0] = av0.w;
        As[a_c0 + 0][a_r1] = av1.x; As[a_c0 + 1][a_r1] = av1.y;
        As[a_c0 + 2][a_r1] = av1.z; As[a_c0 + 3][a_r1] = av1.w;
        const float* Bp = B + (size_t)k0 * Ncols + colBase;
        *(float4*)&Bs[b_r    ][b_c] = *(const float4*)(Bp + (size_t)b_r * Ncols + b_c);
        *(float4*)&Bs[b_r + 8][b_c] = *(const float4*)(Bp + (size_t)(b_r + 8) * Ncols + b_c);
        __syncthreads();
#pragma unroll
        for (int kk = 0; kk < 16; kk++) {
            float4 a0 = *(const float4*)&As[kk][ty * 8];
            float4 a1 = *(const float4*)&As[kk][ty * 8 + 4];
            float4 b0 = *(const float4*)&Bs[kk][tx * 8];
            float4 b1 = *(const float4*)&Bs[kk][tx * 8 + 4];
            float ar[8] = {a0.x, a0.y, a0.z, a0.w, a1.x, a1.y, a1.z, a1.w};
            float br[8] = {b0.x, b0.y, b0.z, b0.w, b1.x, b1.y, b1.z, b1.w};
#pragma unroll
            for (int i = 0; i < 8; i++)
#pragma unroll
                for (int j = 0; j < 8; j++)
                    acc[i][j] = fmaf(ar[i], br[j], acc[i][j]);
        }
        __syncthreads();
    }

#pragma unroll
    for (int i = 0; i < 8; i++) {
        int row  = rowBase + ty * 8 + i;
        int orow = row;
        if (EPI == 2) orow = map[row];
#pragma unroll
        for (int j = 0; j < 8; j += 4) {
            int col = colBase + tx * 8 + j;
            float4 bv = *(const float4*)(bias + col);
            float4 r;
            r.x = acc[i][j + 0] + bv.x;
            r.y = acc[i][j + 1] + bv.y;
            r.z = acc[i][j + 2] + bv.z;
            r.w = acc[i][j + 3] + bv.w;
            if (EPI == 1) {
                r.x = 0.5f * r.x * (1.0f + erff(r.x * 0.7071067811865475f));
                r.y = 0.5f * r.y * (1.0f + erff(r.y * 0.7071067811865475f));
                r.z = 0.5f * r.z * (1.0f + erff(r.z * 0.7071067811865475f));
                r.w = 0.5f * r.w * (1.0f + erff(r.w * 0.7071067811865475f));
            }
            if (EPI == 2) {
                float4 xr = *(const float4*)(resid + (size_t)orow * Ncols + col);
                r.x += xr.x; r.y += xr.y; r.z += xr.z; r.w += xr.w;
            }
            if (EPI == 3) {
                float4 pr = *(const float4*)(Cout + (size_t)row * Ncols + col);
                r.x += pr.x; r.y += pr.y; r.z += pr.z; r.w += pr.w;
            }
            *(float4*)(Cout + (size_t)orow * Ncols + col) = r;
        }
    }
}

// ---------------- per-window attention: one block per (b, w, head) --------
__global__ void __launch_bounds__(256) attn_kernel(
    const float* __restrict__ qkv, const float* __restrict__ mask,
    float* __restrict__ out)
{
    __shared__ float sq[49 * 32];
    __shared__ float sk[49 * 33];   // padded: kills 32-way conflicts in QK^T
    __shared__ float sv[49 * 32];
    __shared__ float ss[49 * 49];
    int w = blockIdx.x, head = blockIdx.y, b = blockIdx.z;
    int tid = threadIdx.x;
    size_t wbase = (size_t)(b * NWIN + w) * 49;
    const float* qp = qkv + wbase * 768 + head * 32;

    for (int idx = tid; idx < 49 * 32; idx += 256) {
        int p = idx >> 5, d = idx & 31;
        const float* rp = qp + (size_t)p * 768 + d;
        sq[idx]         = rp[0];
        sk[p * 33 + d]  = rp[256];
        sv[idx]         = rp[512];
    }
    __syncthreads();

    const float* mw = mask + (size_t)w * 49 * 49;
    for (int idx = tid; idx < 49 * 49; idx += 256) {
        int p = idx / 49, p2 = idx - p * 49;
        float acc = 0.0f;
#pragma unroll
        for (int d = 0; d < 32; d++) acc += sq[p * 32 + d] * sk[p2 * 33 + d];
        ss[idx] = acc * 0.17677669529663687f + mw[idx];   // 1/sqrt(32)
    }
    __syncthreads();

    // softmax: 8 warps, each handles rows wrp, wrp+8, ...
    int wrp = tid >> 5, lane = tid & 31;
    for (int r = wrp; r < 49; r += 8) {
        float v0 = ss[r * 49 + lane];
        float v1 = (lane + 32 < 49) ? ss[r * 49 + lane + 32] : -1e30f;
        float m = fmaxf(v0, v1);
#pragma unroll
        for (int o = 16; o; o >>= 1) m = fmaxf(m, __shfl_xor_sync(0xffffffffu, m, o));
        float e0 = __expf(v0 - m);
        float e1 = (lane + 32 < 49) ? __expf(v1 - m) : 0.0f;
        float sum = e0 + e1;
#pragma unroll
        for (int o = 16; o; o >>= 1) sum += __shfl_xor_sync(0xffffffffu, sum, o);
        float inv = 1.0f / sum;
        ss[r * 49 + lane] = e0 * inv;
        if (lane + 32 < 49) ss[r * 49 + lane + 32] = e1 * inv;
    }
    __syncthreads();

    float* op = out + wbase * 256 + head * 32;
    for (int idx = tid; idx < 49 * 32; idx += 256) {
        int p = idx >> 5, d = idx & 31;
        float acc = 0.0f;
#pragma unroll
        for (int k2 = 0; k2 < 49; k2++) acc += ss[p * 49 + k2] * sv[k2 * 32 + d];
        op[(size_t)p * 256 + d] = acc;
    }
}

// ---------------- launch sequence ----------------
extern "C" void kernel_launch(void* const* d_in, const int* in_sizes, int n_in,
                              void* d_out, int out_size)
{
    const float* x      = (const float*)d_in[0];
    const float* mask   = (const float*)d_in[1];
    const float* n1g    = (const float*)d_in[2];
    const float* n1b    = (const float*)d_in[3];
    const float* qkv_w  = (const float*)d_in[4];
    const float* qkv_b  = (const float*)d_in[5];
    const float* proj_w = (const float*)d_in[6];
    const float* proj_b = (const float*)d_in[7];
    const float* n2g    = (const float*)d_in[8];
    const float* n2b    = (const float*)d_in[9];
    const float* fc1_w  = (const float*)d_in[10];
    const float* fc1_b  = (const float*)d_in[11];
    const float* fc2_w  = (const float*)d_in[12];
    const float* fc2_b  = (const float*)d_in[13];
    float* out = (float*)d_out;

    float *xln, *qkv, *attn, *hid; int* map;
    cudaGetSymbolAddress((void**)&xln,  g_xln);
    cudaGetSymbolAddress((void**)&qkv,  g_qkv);
    cudaGetSymbolAddress((void**)&attn, g_attn);
    cudaGetSymbolAddress((void**)&hid,  g_hid);
    cudaGetSymbolAddress((void**)&map,  g_map);

    // 1. permutation map (shift-roll + window partition, bijection)
    build_map_kernel<<<(M_ROWS + 255) / 256, 256>>>(map);
    // 2. LN1
    ln_kernel<<<M_ROWS / 8, 256>>>(x, n1g, n1b, xln);
    // 3. QKV = gather(xln)[window order] @ qkv_w + b   (M x 768, K=256)
    sgemm_kernel<true, 0><<<dim3(6, 784), 256>>>(xln, qkv_w, qkv_b, qkv, nullptr, map, 256, 768);
    // 4. windowed attention (softmax(QK^T/sqrt(d)+mask) V), per (b,w,head)
    attn_kernel<<<dim3(256, 8, 8), 256>>>(qkv, mask, attn);
    // 5. proj + scatter back + residual from x -> d_out holds x1
    sgemm_kernel<false, 2><<<dim3(2, 784), 256>>>(attn, proj_w, proj_b, out, x, map, 256, 256);
    // 6. LN2 on x1
    ln_kernel<<<M_ROWS / 8, 256>>>(out, n2g, n2b, xln);
    // 7. fc1 + exact GELU  (M x 1024, K=256)
    sgemm_kernel<false, 1><<<dim3(8, 784), 256>>>(xln, fc1_w, fc1_b, hid, nullptr, map, 256, 1024);
    // 8. fc2 + in-place residual on d_out  (M x 256, K=1024)
    sgemm_kernel<false, 3><<<dim3(2, 784), 256>>>(hid, fc2_w, fc2_b, out, nullptr, map, 1024, 256);
}

// round 3
// speedup vs baseline: 1.5196x; 1.5196x over previous
#include <cuda_runtime.h>
#include <math.h>
#include <stdint.h>

// ---------------- problem constants ----------------
#define M_ROWS 100352            // B * N = 8 * 12544
#define NWIN   256               // 16 * 16 windows

// ---------------- scratch (static device globals; no allocations) ----------
__device__ float g_xln [(size_t)M_ROWS * 256];
__device__ float g_qkv [(size_t)M_ROWS * 768];
__device__ float g_attn[(size_t)M_ROWS * 256];
__device__ float g_hid [(size_t)M_ROWS * 1024];
__device__ int   g_map [M_ROWS];
__device__ float g_bt  [786432];                 // transposed weights [N,K]
#define BT_QKV  0
#define BT_PROJ 196608
#define BT_FC1  262144
#define BT_FC2  524288

// ---------------- permutation map ----------------
__global__ void build_map_kernel(int* __restrict__ map) {
    int i = blockIdx.x * 256 + threadIdx.x;
    if (i >= M_ROWS) return;
    int b   = i / (NWIN * 49);
    int rem = i - b * (NWIN * 49);
    int w   = rem / 49;
    int p   = rem - w * 49;
    int wh = w >> 4, ww = w & 15;
    int ii = p / 7,  jj = p - ii * 7;
    int h  = wh * 7 + ii + 3; if (h  >= 112) h  -= 112;
    int wg = ww * 7 + jj + 3; if (wg >= 112) wg -= 112;
    map[i] = b * 12544 + h * 112 + wg;
}

// ---------------- weight transpose [R,Cc] -> [Cc,R] ----------------
__global__ void transpose_kernel(const float* __restrict__ in, float* __restrict__ out,
                                 int R, int Cc) {
    __shared__ float t[32][33];
    int c = blockIdx.x * 32 + threadIdx.x;
    int r = blockIdx.y * 32 + threadIdx.y;
#pragma unroll
    for (int i = 0; i < 32; i += 8)
        t[threadIdx.y + i][threadIdx.x] = in[(size_t)(r + i) * Cc + c];
    __syncthreads();
    int oc = blockIdx.y * 32 + threadIdx.x;
    int orow = blockIdx.x * 32 + threadIdx.y;
#pragma unroll
    for (int i = 0; i < 32; i += 8)
        out[(size_t)(orow + i) * R + oc] = t[threadIdx.x][threadIdx.y + i];
}

// ---------------- LayerNorm ----------------
__global__ void __launch_bounds__(256) ln_kernel(
    const float* __restrict__ x, const float* __restrict__ gamma,
    const float* __restrict__ beta, float* __restrict__ out)
{
    int row  = (blockIdx.x * 256 + threadIdx.x) >> 5;
    int lane = threadIdx.x & 31;
    const float* xr = x + (size_t)row * 256 + lane * 8;
    float4 a = *(const float4*)(xr);
    float4 c = *(const float4*)(xr + 4);
    float s  = a.x + a.y + a.z + a.w + c.x + c.y + c.z + c.w;
    float sq = a.x*a.x + a.y*a.y + a.z*a.z + a.w*a.w
             + c.x*c.x + c.y*c.y + c.z*c.z + c.w*c.w;
#pragma unroll
    for (int o = 16; o; o >>= 1) {
        s  += __shfl_xor_sync(0xffffffffu, s,  o);
        sq += __shfl_xor_sync(0xffffffffu, sq, o);
    }
    float mean = s  * (1.0f / 256.0f);
    float var  = sq * (1.0f / 256.0f) - mean * mean;
    float rstd = rsqrtf(var + 1e-5f);
    float4 g0 = *(const float4*)(gamma + lane * 8);
    float4 g1 = *(const float4*)(gamma + lane * 8 + 4);
    float4 b0 = *(const float4*)(beta  + lane * 8);
    float4 b1 = *(const float4*)(beta  + lane * 8 + 4);
    float4 r0, r1;
    r0.x = (a.x - mean) * rstd * g0.x + b0.x;
    r0.y = (a.y - mean) * rstd * g0.y + b0.y;
    r0.z = (a.z - mean) * rstd * g0.z + b0.z;
    r0.w = (a.w - mean) * rstd * g0.w + b0.w;
    r1.x = (c.x - mean) * rstd * g1.x + b1.x;
    r1.y = (c.y - mean) * rstd * g1.y + b1.y;
    r1.z = (c.z - mean) * rstd * g1.z + b1.z;
    r1.w = (c.w - mean) * rstd * g1.w + b1.w;
    float* orow = out + (size_t)row * 256 + lane * 8;
    *(float4*)(orow)     = r0;
    *(float4*)(orow + 4) = r1;
}

// ================= mma.sync tf32 GEMM =================
// Block tile 128x128, K-chunk 32, 256 threads = 8 warps (4x2), warp tile 32x64.
// A: [M,K] fp32 (optionally row-gathered). Bt: [N,K] fp32. D = A @ Bt^T.
// EPI: 0 bias; 1 bias+GELU; 2 bias+scatter(map)+resid; 3 bias+inplace resid.
#define PADK 36                      // 32 + 4 -> conflict-free fragment LDS
#define S_BUF (128 * PADK)           // uints per operand buffer
#define GEMM_SMEM (4 * S_BUF * 4)    // bytes: A0 B0 A1 B1

__device__ __forceinline__ void mma_m16n8k8(float* c, const uint32_t* a, const uint32_t* b) {
    asm volatile(
        "mma.sync.aligned.m16n8k8.row.col.f32.tf32.tf32.f32 "
        "{%0,%1,%2,%3}, {%4,%5,%6,%7}, {%8,%9}, {%0,%1,%2,%3};"
        : "+f"(c[0]), "+f"(c[1]), "+f"(c[2]), "+f"(c[3])
        : "r"(a[0]), "r"(a[1]), "r"(a[2]), "r"(a[3]), "r"(b[0]), "r"(b[1]));
}
__device__ __forceinline__ uint32_t f2tf32(float f) {
    uint32_t u;
    asm("cvt.rna.tf32.f32 %0, %1;" : "=r"(u) : "f"(f));
    return u;
}

template<bool GATHER_A, int EPI>
__global__ void __launch_bounds__(256) mma_gemm(
    const float* __restrict__ A, const float* __restrict__ Bt,
    const float* __restrict__ bias, float* __restrict__ Cout,
    const float* __restrict__ resid, const int* __restrict__ map,
    int Kdim, int Ncols)
{
    extern __shared__ uint32_t sm[];
    uint32_t* bufA[2] = { sm,             sm + 2 * S_BUF };
    uint32_t* bufB[2] = { sm + S_BUF,     sm + 3 * S_BUF };

    const int tid = threadIdx.x;
    const int wid = tid >> 5, lane = tid & 31;
    const int warp_m = wid & 3, warp_n = wid >> 2;
    const int g = lane >> 2, tig = lane & 3;
    const int rowBase = blockIdx.y * 128;
    const int colBase = blockIdx.x * 128;

    // gmem load assignment: thread t -> row t>>1, k-offset (t&1)*16, 4 x float4
    const int lrow = tid >> 1;
    const int lcol = (tid & 1) * 16;
    int arow = rowBase + lrow;
    if (GATHER_A) arow = map[arow];
    const float* Ap = A  + (size_t)arow * Kdim + lcol;
    const float* Bp = Bt + (size_t)(colBase + lrow) * Kdim + lcol;
    const int sbase = lrow * PADK + lcol;

    float acc[2][8][4];
#pragma unroll
    for (int ma = 0; ma < 2; ma++)
#pragma unroll
        for (int na = 0; na < 8; na++)
#pragma unroll
            for (int q = 0; q < 4; q++) acc[ma][na][q] = 0.0f;

    const int nc = Kdim >> 5;

    // prologue: chunk 0 -> buf0
    {
        float4 ra[4], rb[4];
#pragma unroll
        for (int i = 0; i < 4; i++) { ra[i] = *(const float4*)(Ap + i * 4); rb[i] = *(const float4*)(Bp + i * 4); }
#pragma unroll
        for (int i = 0; i < 4; i++) {
            uint4 ua = { f2tf32(ra[i].x), f2tf32(ra[i].y), f2tf32(ra[i].z), f2tf32(ra[i].w) };
            uint4 ub = { f2tf32(rb[i].x), f2tf32(rb[i].y), f2tf32(rb[i].z), f2tf32(rb[i].w) };
            *(uint4*)(bufA[0] + sbase + i * 4) = ua;
            *(uint4*)(bufB[0] + sbase + i * 4) = ub;
        }
    }
    __syncthreads();

    for (int c = 0; c < nc; c++) {
        float4 ra[4], rb[4];
        const bool more = (c + 1 < nc);
        if (more) {
            int k0 = (c + 1) * 32;
#pragma unroll
            for (int i = 0; i < 4; i++) { ra[i] = *(const float4*)(Ap + k0 + i * 4); rb[i] = *(const float4*)(Bp + k0 + i * 4); }
        }
        const uint32_t* As = bufA[c & 1];
        const uint32_t* Bs = bufB[c & 1];
#pragma unroll
        for (int ks = 0; ks < 4; ks++) {
            uint32_t af[2][4];
#pragma unroll
            for (int ma = 0; ma < 2; ma++) {
                int r0 = warp_m * 32 + ma * 16 + g;
                af[ma][0] = As[r0 * PADK + ks * 8 + tig];
                af[ma][1] = As[(r0 + 8) * PADK + ks * 8 + tig];
                af[ma][2] = As[r0 * PADK + ks * 8 + tig + 4];
                af[ma][3] = As[(r0 + 8) * PADK + ks * 8 + tig + 4];
            }
#pragma unroll
            for (int na = 0; na < 8; na++) {
                int nrow = warp_n * 64 + na * 8 + g;
                uint32_t bf[2];
                bf[0] = Bs[nrow * PADK + ks * 8 + tig];
                bf[1] = Bs[nrow * PADK + ks * 8 + tig + 4];
                mma_m16n8k8(acc[0][na], af[0], bf);
                mma_m16n8k8(acc[1][na], af[1], bf);
            }
        }
        if (more) {
            uint32_t* nA = bufA[(c + 1) & 1];
            uint32_t* nB = bufB[(c + 1) & 1];
#pragma unroll
            for (int i = 0; i < 4; i++) {
                uint4 ua = { f2tf32(ra[i].x), f2tf32(ra[i].y), f2tf32(ra[i].z), f2tf32(ra[i].w) };
                uint4 ub = { f2tf32(rb[i].x), f2tf32(rb[i].y), f2tf32(rb[i].z), f2tf32(rb[i].w) };
                *(uint4*)(nA + sbase + i * 4) = ua;
                *(uint4*)(nB + sbase + i * 4) = ub;
            }
        }
        __syncthreads();
    }

    // ---------------- epilogue straight from accumulators ----------------
#pragma unroll
    for (int ma = 0; ma < 2; ma++) {
        int r0 = rowBase + warp_m * 32 + ma * 16 + g;
        int r1 = r0 + 8;
        int or0 = (EPI == 2) ? map[r0] : r0;
        int or1 = (EPI == 2) ? map[r1] : r1;
#pragma unroll
        for (int na = 0; na < 8; na++) {
            int col = colBase + warp_n * 64 + na * 8 + 2 * tig;
            float2 bv = *(const float2*)(bias + col);
            float2 o0, o1;
            o0.x = acc[ma][na][0] + bv.x;  o0.y = acc[ma][na][1] + bv.y;
            o1.x = acc[ma][na][2] + bv.x;  o1.y = acc[ma][na][3] + bv.y;
            if (EPI == 1) {
                o0.x = 0.5f * o0.x * (1.0f + erff(o0.x * 0.7071067811865475f));
                o0.y = 0.5f * o0.y * (1.0f + erff(o0.y * 0.7071067811865475f));
                o1.x = 0.5f * o1.x * (1.0f + erff(o1.x * 0.7071067811865475f));
                o1.y = 0.5f * o1.y * (1.0f + erff(o1.y * 0.7071067811865475f));
            }
            if (EPI == 2) {
                float2 x0 = *(const float2*)(resid + (size_t)or0 * Ncols + col);
                float2 x1 = *(const float2*)(resid + (size_t)or1 * Ncols + col);
                o0.x += x0.x; o0.y += x0.y; o1.x += x1.x; o1.y += x1.y;
            }
            if (EPI == 3) {
                float2 p0 = *(const float2*)(Cout + (size_t)r0 * Ncols + col);
                float2 p1 = *(const float2*)(Cout + (size_t)r1 * Ncols + col);
                o0.x += p0.x; o0.y += p0.y; o1.x += p1.x; o1.y += p1.y;
            }
            *(float2*)(Cout + (size_t)or0 * Ncols + col) = o0;
            *(float2*)(Cout + (size_t)or1 * Ncols + col) = o1;
        }
    }
}

// ---------------- per-window attention, register-blocked ----------------
__global__ void __launch_bounds__(256) attn_kernel(
    const float* __restrict__ qkv, const float* __restrict__ mask,
    float* __restrict__ out)
{
    __shared__ float sq[49 * 32];
    __shared__ float sk[49 * 33];
    __shared__ float sv[49 * 32];
    __shared__ float ss[49 * 49];
    int w = blockIdx.x, head = blockIdx.y, b = blockIdx.z;
    int tid = threadIdx.x;
    size_t wbase = (size_t)(b * NWIN + w) * 49;
    const float* qp = qkv + wbase * 768 + head * 32;

    for (int idx = tid; idx < 49 * 32; idx += 256) {
        int p = idx >> 5, d = idx & 31;
        const float* rp = qp + (size_t)p * 768 + d;
        sq[idx]        = rp[0];
        sk[p * 33 + d] = rp[256];
        sv[idx]        = rp[512];
    }
    __syncthreads();

    int wrp = tid >> 5, lane = tid & 31;
    const float* mw = mask + (size_t)w * 2401;

    {
        float acc0[7], acc1[7];
#pragma unroll
        for (int i = 0; i < 7; i++) { acc0[i] = 0.0f; acc1[i] = 0.0f; }
        int l2 = lane + 32;
        bool has2 = l2 < 49;
#pragma unroll 8
        for (int d = 0; d < 32; d++) {
            float k0 = sk[lane * 33 + d];
            float k1 = has2 ? sk[l2 * 33 + d] : 0.0f;
#pragma unroll
            for (int i = 0; i < 7; i++) {
                int r = wrp + i * 8;
                if (r < 49) {
                    float qd = sq[r * 32 + d];
                    acc0[i] += qd * k0;
                    acc1[i] += qd * k1;
                }
            }
        }
#pragma unroll
        for (int i = 0; i < 7; i++) {
            int r = wrp + i * 8;
            if (r < 49) {
                ss[r * 49 + lane] = acc0[i] * 0.17677669529663687f + mw[r * 49 + lane];
                if (has2) ss[r * 49 + l2] = acc1[i] * 0.17677669529663687f + mw[r * 49 + l2];
            }
        }
    }
    __syncthreads();

    for (int r = wrp; r < 49; r += 8) {
        float v0 = ss[r * 49 + lane];
        float v1 = (lane + 32 < 49) ? ss[r * 49 + lane + 32] : -1e30f;
        float m = fmaxf(v0, v1);
#pragma unroll
        for (int o = 16; o; o >>= 1) m = fmaxf(m, __shfl_xor_sync(0xffffffffu, m, o));
        float e0 = __expf(v0 - m);
        float e1 = (lane + 32 < 49) ? __expf(v1 - m) : 0.0f;
        float sum = e0 + e1;
#pragma unroll
        for (int o = 16; o; o >>= 1) sum += __shfl_xor_sync(0xffffffffu, sum, o);
        float inv = 1.0f / sum;
        ss[r * 49 + lane] = e0 * inv;
        if (lane + 32 < 49) ss[r * 49 + lane + 32] = e1 * inv;
    }
    __syncthreads();

    {
        float acc[7];
#pragma unroll
        for (int i = 0; i < 7; i++) acc[i] = 0.0f;
#pragma unroll 7
        for (int k2 = 0; k2 < 49; k2++) {
            float vv = sv[k2 * 32 + lane];
#pragma unroll
            for (int i = 0; i < 7; i++) {
                int p = wrp + i * 8;
                if (p < 49) acc[i] += ss[p * 49 + k2] * vv;
            }
        }
        float* op = out + wbase * 256 + head * 32;
#pragma unroll
        for (int i = 0; i < 7; i++) {
            int p = wrp + i * 8;
            if (p < 49) op[(size_t)p * 256 + lane] = acc[i];
        }
    }
}

// ---------------- launch sequence ----------------
extern "C" void kernel_launch(void* const* d_in, const int* in_sizes, int n_in,
                              void* d_out, int out_size)
{
    const float* x      = (const float*)d_in[0];
    const float* mask   = (const float*)d_in[1];
    const float* n1g    = (const float*)d_in[2];
    const float* n1b    = (const float*)d_in[3];
    const float* qkv_w  = (const float*)d_in[4];
    const float* qkv_b  = (const float*)d_in[5];
    const float* proj_w = (const float*)d_in[6];
    const float* proj_b = (const float*)d_in[7];
    const float* n2g    = (const float*)d_in[8];
    const float* n2b    = (const float*)d_in[9];
    const float* fc1_w  = (const float*)d_in[10];
    const float* fc1_b  = (const float*)d_in[11];
    const float* fc2_w  = (const float*)d_in[12];
    const float* fc2_b  = (const float*)d_in[13];
    float* out = (float*)d_out;

    float *xln, *qkv, *attn, *hid, *bt; int* map;
    cudaGetSymbolAddress((void**)&xln,  g_xln);
    cudaGetSymbolAddress((void**)&qkv,  g_qkv);
    cudaGetSymbolAddress((void**)&attn, g_attn);
    cudaGetSymbolAddress((void**)&hid,  g_hid);
    cudaGetSymbolAddress((void**)&map,  g_map);
    cudaGetSymbolAddress((void**)&bt,   g_bt);

    cudaFuncSetAttribute(mma_gemm<true, 0>,  cudaFuncAttributeMaxDynamicSharedMemorySize, GEMM_SMEM);
    cudaFuncSetAttribute(mma_gemm<false, 1>, cudaFuncAttributeMaxDynamicSharedMemorySize, GEMM_SMEM);
    cudaFuncSetAttribute(mma_gemm<false, 2>, cudaFuncAttributeMaxDynamicSharedMemorySize, GEMM_SMEM);
    cudaFuncSetAttribute(mma_gemm<false, 3>, cudaFuncAttributeMaxDynamicSharedMemorySize, GEMM_SMEM);

    dim3 tb(32, 8);
    transpose_kernel<<<dim3(24, 8),  tb>>>(qkv_w,  bt + BT_QKV,  256, 768);
    transpose_kernel<<<dim3(8, 8),   tb>>>(proj_w, bt + BT_PROJ, 256, 256);
    transpose_kernel<<<dim3(32, 8),  tb>>>(fc1_w,  bt + BT_FC1,  256, 1024);
    transpose_kernel<<<dim3(8, 32),  tb>>>(fc2_w,  bt + BT_FC2,  1024, 256);

    build_map_kernel<<<(M_ROWS + 255) / 256, 256>>>(map);
    ln_kernel<<<M_ROWS / 8, 256>>>(x, n1g, n1b, xln);
    // QKV (gathered A), N=768, K=256
    mma_gemm<true, 0><<<dim3(6, 784), 256, GEMM_SMEM>>>(xln, bt + BT_QKV, qkv_b, qkv, nullptr, map, 256, 768);
    // windowed attention
    attn_kernel<<<dim3(256, 8, 8), 256>>>(qkv, mask, attn);
    // proj + scatter + residual(x) -> d_out
    mma_gemm<false, 2><<<dim3(2, 784), 256, GEMM_SMEM>>>(attn, bt + BT_PROJ, proj_b, out, x, map, 256, 256);
    ln_kernel<<<M_ROWS / 8, 256>>>(out, n2g, n2b, xln);
    // fc1 + GELU, N=1024, K=256
    mma_gemm<false, 1><<<dim3(8, 784), 256, GEMM_SMEM>>>(xln, bt + BT_FC1, fc1_b, hid, nullptr, map, 256, 1024);
    // fc2 + in-place residual, N=256, K=1024
    mma_gemm<false, 3><<<dim3(2, 784), 256, GEMM_SMEM>>>(hid, bt + BT_FC2, fc2_b, out, nullptr, map, 1024, 256);
}